// round 15
// baseline (speedup 1.0000x reference)
#include <cuda_runtime.h>
#include <cuda_bf16.h>
#include <cstdint>

#define BB 8
#define CC 256
#define NN 16384
#define NSPLIT 16
static const long CN = (long)CC * NN;

// ---------------- device scratch ----------------
__device__ float d_s0[BB * CC];
__device__ float d_s1[BB * CC];
__device__ float d_Mpart[(size_t)NSPLIT * BB * CC * CC];
__device__ float d_M[BB * CC * CC];
__device__ float d_T1[BB * CC * CC];
__device__ float d_fraw[BB * CC * CC];
__device__ float d_fS[BB * CC * CC];
__device__ float d_A2[BB * CC * CC];
__device__ float d_tvec[BB * CC];
__device__ float d_pvec[BB * CC];
__device__ float d_cvec[BB * CC];
__device__ float d_yT[(size_t)BB * NN * CC];

// ---------------- helpers ----------------
// packed split: hi = bf16x2(a,b), lo = bf16x2 of residuals. ~6 instructions.
__device__ __forceinline__ void split_pack2(float a, float b, uint32_t& hi, uint32_t& lo) {
    asm("cvt.rn.bf16x2.f32 %0, %1, %2;" : "=r"(hi) : "f"(b), "f"(a));
    float ha = __uint_as_float(hi << 16);           // f32 of bf16(a)
    float hb = __uint_as_float(hi & 0xffff0000u);   // f32 of bf16(b)
    asm("cvt.rn.bf16x2.f32 %0, %1, %2;" : "=r"(lo) : "f"(b - hb), "f"(a - ha));
}

__device__ __forceinline__ void mma_bf16(float* c, const uint32_t* a, const uint32_t* b) {
    asm volatile(
        "mma.sync.aligned.m16n8k16.row.col.f32.bf16.bf16.f32 "
        "{%0,%1,%2,%3},{%4,%5,%6,%7},{%8,%9},{%0,%1,%2,%3};"
        : "+f"(c[0]), "+f"(c[1]), "+f"(c[2]), "+f"(c[3])
        : "r"(a[0]), "r"(a[1]), "r"(a[2]), "r"(a[3]), "r"(b[0]), "r"(b[1]));
}

#define BK 32
#define KP 16            // k-pairs per chunk
#define ST 20            // smem row stride in b32 (pad 4) -> conflict-free frags
#define LAYER (128 * ST) // one hi/lo plane: 2560 u32
#define BUFU32 (4 * LAYER)
#define SMEM_BYTES (2 * BUFU32 * 4)  // double buffer: 81920 B

// ---------------- tensor-core GEMM: C[128m,128n] = A[128,K] * B[128n,K]^T ----------------
// A element [m][k]: ATRANS=0 -> Ap + m*aRS + k ; ATRANS=1 -> Ap + k*aRS + m
// B element [n][k]: BTRANS=0 -> Bp + n*bRS + k ; BTRANS=1 -> Bp + k*bRS + n
// BIAS: 0 none, 1 per-m-row, 2 per-n-col.  SUMS: atomicAdd fp32 row sums (gram only).
// Double-buffered smem: stage chunk ch+1 while computing chunk ch, ONE sync per chunk.
template <int ATRANS, int BTRANS, int BIAS, int SUMS>
__global__ __launch_bounds__(256, 2) void tc(
    const float* __restrict__ A, long aB, long aMT, long aS, long aRS,
    const float* __restrict__ B, long bB, long bNT, long bS, long bRS,
    float* __restrict__ C, long cB, long cS, long cMT, long cNT, long cLD,
    const float* __restrict__ bias, long biasB,
    float* __restrict__ sumA, float* __restrict__ sumB,
    int K, int nS, int nMT, int nNT) {
    extern __shared__ __align__(16) uint32_t smemRaw[];

    const int tid = threadIdx.x;
    const int lane = tid & 31;
    const int wid = tid >> 5;
    const int wm = wid >> 1;   // 0..3
    const int wn = wid & 1;    // 0..1
    const int g = lane >> 2;   // group row 0..7
    const int t4 = lane & 3;   // 0..3

    int z = blockIdx.x;
    const int nt = z % nNT; z /= nNT;
    const int mt = z % nMT; z /= nMT;
    const int s = z % nS;
    const int b = z / nS;

    const float* Ap = A + (size_t)b * aB + (size_t)mt * aMT + (size_t)s * aS;
    const float* Bp = B + (size_t)b * bB + (size_t)nt * bNT + (size_t)s * bS;
    float* Cp = C + (size_t)b * cB + (size_t)s * cS + (size_t)mt * cMT + (size_t)nt * cNT;

    float acc[2][8][4];
#pragma unroll
    for (int i = 0; i < 2; i++)
#pragma unroll
        for (int j = 0; j < 8; j++)
#pragma unroll
            for (int q = 0; q < 4; q++) acc[i][j][q] = 0.f;

    // ---- staging into a given buffer ----
    auto stage = [&](uint32_t* buf, int kt) {
        uint32_t* sAhi = buf;
        uint32_t* sAlo = buf + LAYER;
        uint32_t* sBhi = buf + 2 * LAYER;
        uint32_t* sBlo = buf + 3 * LAYER;
        if (!ATRANS) {
#pragma unroll
            for (int i = tid; i < 128 * 8; i += 256) {
                int r = i >> 3, q = i & 7;
                float4 v = *(const float4*)(Ap + (size_t)r * aRS + kt + 4 * q);
                uint32_t h0, l0, h1, l1;
                split_pack2(v.x, v.y, h0, l0);
                split_pack2(v.z, v.w, h1, l1);
                *(uint2*)&sAhi[r * ST + 2 * q] = make_uint2(h0, h1);
                *(uint2*)&sAlo[r * ST + 2 * q] = make_uint2(l0, l1);
                if (SUMS && nt == 0) {
                    float red = (v.x + v.y) + (v.z + v.w);
#pragma unroll
                    for (int qq = 4; qq; qq >>= 1) red += __shfl_xor_sync(0xffffffffu, red, qq);
                    if ((lane & 7) == 0) atomicAdd(&sumA[(size_t)b * CC + mt * 128 + r], red);
                }
            }
        } else {
#pragma unroll
            for (int i = tid; i < 128 * KP; i += 256) {
                int m = i & 127, cp = i >> 7;
                float v0 = Ap[(size_t)(kt + 2 * cp) * aRS + m];
                float v1 = Ap[(size_t)(kt + 2 * cp + 1) * aRS + m];
                uint32_t hi, lo;
                split_pack2(v0, v1, hi, lo);
                sAhi[m * ST + cp] = hi;
                sAlo[m * ST + cp] = lo;
            }
        }
        if (!BTRANS) {
#pragma unroll
            for (int i = tid; i < 128 * 8; i += 256) {
                int r = i >> 3, q = i & 7;
                float4 v = *(const float4*)(Bp + (size_t)r * bRS + kt + 4 * q);
                uint32_t h0, l0, h1, l1;
                split_pack2(v.x, v.y, h0, l0);
                split_pack2(v.z, v.w, h1, l1);
                *(uint2*)&sBhi[r * ST + 2 * q] = make_uint2(h0, h1);
                *(uint2*)&sBlo[r * ST + 2 * q] = make_uint2(l0, l1);
                if (SUMS && mt == 0) {
                    float red = (v.x + v.y) + (v.z + v.w);
#pragma unroll
                    for (int qq = 4; qq; qq >>= 1) red += __shfl_xor_sync(0xffffffffu, red, qq);
                    if ((lane & 7) == 0) atomicAdd(&sumB[(size_t)b * CC + nt * 128 + r], red);
                }
            }
        } else {
#pragma unroll
            for (int i = tid; i < 128 * KP; i += 256) {
                int n = i & 127, cp = i >> 7;
                float v0 = Bp[(size_t)(kt + 2 * cp) * bRS + n];
                float v1 = Bp[(size_t)(kt + 2 * cp + 1) * bRS + n];
                uint32_t hi, lo;
                split_pack2(v0, v1, hi, lo);
                sBhi[n * ST + cp] = hi;
                sBlo[n * ST + cp] = lo;
            }
        }
    };

    // ---- compute from a given buffer ----
    auto compute = [&](const uint32_t* buf) {
        const uint32_t* sAhi = buf;
        const uint32_t* sAlo = buf + LAYER;
        const uint32_t* sBhi = buf + 2 * LAYER;
        const uint32_t* sBlo = buf + 3 * LAYER;
#pragma unroll
        for (int kk = 0; kk < 2; kk++) {
            const int kb = kk * 8;
            uint32_t af[2][2][4];
#pragma unroll
            for (int mi = 0; mi < 2; mi++) {
                int r = wm * 32 + mi * 16 + g;
#pragma unroll
                for (int p = 0; p < 2; p++) {
                    const uint32_t* S = p ? sAlo : sAhi;
                    af[mi][p][0] = S[r * ST + kb + t4];
                    af[mi][p][1] = S[(r + 8) * ST + kb + t4];
                    af[mi][p][2] = S[r * ST + kb + t4 + 4];
                    af[mi][p][3] = S[(r + 8) * ST + kb + t4 + 4];
                }
            }
            uint32_t bf[8][2][2];
#pragma unroll
            for (int ni = 0; ni < 8; ni++) {
                int n = wn * 64 + ni * 8 + g;
#pragma unroll
                for (int p = 0; p < 2; p++) {
                    const uint32_t* S = p ? sBlo : sBhi;
                    bf[ni][p][0] = S[n * ST + kb + t4];
                    bf[ni][p][1] = S[n * ST + kb + t4 + 4];
                }
            }
#pragma unroll
            for (int mi = 0; mi < 2; mi++)
#pragma unroll
                for (int ni = 0; ni < 8; ni++) {
                    mma_bf16(acc[mi][ni], af[mi][0], bf[ni][0]);  // hi*hi
                    mma_bf16(acc[mi][ni], af[mi][0], bf[ni][1]);  // hi*lo
                    mma_bf16(acc[mi][ni], af[mi][1], bf[ni][0]);  // lo*hi
                }
        }
    };

    // ---- double-buffered mainloop: ONE sync per chunk ----
    const int nch = K / BK;
    stage(smemRaw, 0);
    __syncthreads();
    for (int ch = 0; ch < nch; ch++) {
        uint32_t* cur = smemRaw + (ch & 1) * BUFU32;
        uint32_t* nxt = smemRaw + ((ch + 1) & 1) * BUFU32;
        if (ch + 1 < nch) stage(nxt, (ch + 1) * BK);  // LDGs issue first, overlap compute
        compute(cur);
        __syncthreads();
    }

    // ---- epilogue ----
#pragma unroll
    for (int mi = 0; mi < 2; mi++) {
        int r0 = wm * 32 + mi * 16 + g;
        float bm0 = 0.f, bm1 = 0.f;
        if (BIAS == 1) {
            bm0 = bias[(size_t)b * biasB + mt * 128 + r0];
            bm1 = bias[(size_t)b * biasB + mt * 128 + r0 + 8];
        }
#pragma unroll
        for (int ni = 0; ni < 8; ni++) {
            int cn = wn * 64 + ni * 8 + t4 * 2;
            float bc0 = 0.f, bc1 = 0.f;
            if (BIAS == 2) {
                bc0 = bias[(size_t)b * biasB + nt * 128 + cn];
                bc1 = bias[(size_t)b * biasB + nt * 128 + cn + 1];
            }
            float2 v0 = {acc[mi][ni][0] + bm0 + bc0, acc[mi][ni][1] + bm0 + bc1};
            float2 v1 = {acc[mi][ni][2] + bm1 + bc0, acc[mi][ni][3] + bm1 + bc1};
            *(float2*)(Cp + (size_t)r0 * cLD + cn) = v0;
            *(float2*)(Cp + (size_t)(r0 + 8) * cLD + cn) = v1;
        }
    }
}

// ---------------- small kernels ----------------
__global__ void zeroS_kernel() {
    int i = blockIdx.x * 512 + threadIdx.x;
    if (i < BB * CC) { d_s0[i] = 0.f; d_s1[i] = 0.f; }
}
__global__ void reduceM_kernel() {
    int idx = blockIdx.x * 256 + threadIdx.x;
    float acc = 0.f;
#pragma unroll
    for (int s = 0; s < NSPLIT; s++) acc += d_Mpart[(size_t)s * BB * CC * CC + idx];
    d_M[idx] = acc;
}
// one warp per (b,c): tv = theta_w[c,:]·s1[b], pv = phi_w[c,:]·s0[b]
__global__ void tvpv_kernel(const float* __restrict__ theta_w,
                            const float* __restrict__ phi_w) {
    int w = blockIdx.x * 8 + (threadIdx.x >> 5);
    int lane = threadIdx.x & 31;
    int b = w >> 8, c = w & 255;
    float tv = 0.f, pv = 0.f;
#pragma unroll
    for (int i = lane; i < CC; i += 32) {
        float s1v = d_s1[b * CC + i], s0v = d_s0[b * CC + i];
        tv += theta_w[c * CC + i] * s1v;
        pv += phi_w[c * CC + i] * s0v;
    }
#pragma unroll
    for (int q = 16; q; q >>= 1) {
        tv += __shfl_xor_sync(0xffffffffu, tv, q);
        pv += __shfl_xor_sync(0xffffffffu, pv, q);
    }
    if (lane == 0) {
        d_tvec[b * CC + c] = tv;
        d_pvec[b * CC + c] = pv;
    }
}
// tiled softmax over axis c: block = (b, 32-wide d tile); coalesced gmem access
__global__ __launch_bounds__(256) void softmax_kernel(const float* __restrict__ theta_b,
                                                      const float* __restrict__ phi_b) {
    const int b = blockIdx.x >> 3;
    const int d0 = (blockIdx.x & 7) * 32;
    __shared__ float tile[256][33];
    __shared__ float stv[256], stb[256], spb[32], spv[32];
    __shared__ float red[8][33];
    __shared__ float colmax[32], colsum[32];
    const int tid = threadIdx.x;
    const int j = tid & 31, p = tid >> 5;

    if (tid < 256) {
        stv[tid] = d_tvec[b * CC + tid];
        stb[tid] = theta_b[tid];
    }
    if (tid < 32) {
        spb[tid] = phi_b[d0 + tid];
        spv[tid] = d_pvec[b * CC + d0 + tid];
    }
    __syncthreads();

    for (int idx = tid; idx < 256 * 32; idx += 256) {
        int c = idx >> 5, jj = idx & 31;
        float l = d_fraw[((size_t)b * CC + c) * CC + d0 + jj] + spb[jj] * stv[c] +
                  stb[c] * (spv[jj] + (float)NN * spb[jj]);
        tile[c][jj] = l;
    }
    __syncthreads();

    float m = -3.4e38f;
#pragma unroll
    for (int r = 0; r < 32; r++) m = fmaxf(m, tile[p * 32 + r][j]);
    red[p][j] = m;
    __syncthreads();
    if (p == 0) {
        float mm = red[0][j];
#pragma unroll
        for (int q = 1; q < 8; q++) mm = fmaxf(mm, red[q][j]);
        colmax[j] = mm;
    }
    __syncthreads();

    float cm = colmax[j];
    float s = 0.f;
#pragma unroll
    for (int r = 0; r < 32; r++) {
        float e = expf(tile[p * 32 + r][j] - cm);
        tile[p * 32 + r][j] = e;
        s += e;
    }
    red[p][j] = s;
    __syncthreads();
    if (p == 0) {
        float ss = red[0][j];
#pragma unroll
        for (int q = 1; q < 8; q++) ss += red[q][j];
        colsum[j] = 1.f / ss;
    }
    __syncthreads();

    for (int idx = tid; idx < 256 * 32; idx += 256) {
        int c = idx >> 5, jj = idx & 31;
        d_fS[((size_t)b * CC + c) * CC + d0 + jj] = tile[c][jj] * colsum[jj];
    }
}
// one warp per (b,c): cvec = fS[b][c][:]·g_b
__global__ void cvec_kernel(const float* __restrict__ g_b) {
    int w = blockIdx.x * 8 + (threadIdx.x >> 5);
    int lane = threadIdx.x & 31;
    int b = w >> 8, c = w & 255;
    const float* row = d_fS + ((size_t)b * CC + c) * CC;
    float acc = 0.f;
#pragma unroll
    for (int i = lane; i < CC; i += 32) acc += row[i] * g_b[i];
#pragma unroll
    for (int q = 16; q; q >>= 1) acc += __shfl_xor_sync(0xffffffffu, acc, q);
    if (lane == 0) d_cvec[b * CC + c] = acc;
}

// ---------------- launch ----------------
extern "C" void kernel_launch(void* const* d_in, const int* in_sizes, int n_in,
                              void* d_out, int out_size) {
    const float* x0 = (const float*)d_in[0];
    const float* x1 = (const float*)d_in[1];
    const float* g_w = (const float*)d_in[2];
    const float* g_b = (const float*)d_in[3];
    const float* theta_w = (const float*)d_in[4];
    const float* theta_b = (const float*)d_in[5];
    const float* phi_w = (const float*)d_in[6];
    const float* phi_b = (const float*)d_in[7];
    const float* W_w = (const float*)d_in[8];
    const float* W_b = (const float*)d_in[9];
    float* out = (float*)d_out;

    void *pMpart, *pM, *pT1, *pFraw, *pFS, *pA2, *pYT, *pCvec, *pS0, *pS1;
    cudaGetSymbolAddress(&pMpart, d_Mpart);
    cudaGetSymbolAddress(&pM, d_M);
    cudaGetSymbolAddress(&pT1, d_T1);
    cudaGetSymbolAddress(&pFraw, d_fraw);
    cudaGetSymbolAddress(&pFS, d_fS);
    cudaGetSymbolAddress(&pA2, d_A2);
    cudaGetSymbolAddress(&pYT, d_yT);
    cudaGetSymbolAddress(&pCvec, d_cvec);
    cudaGetSymbolAddress(&pS0, d_s0);
    cudaGetSymbolAddress(&pS1, d_s1);

    cudaFuncSetAttribute(tc<0, 0, 0, 1>, cudaFuncAttributeMaxDynamicSharedMemorySize, SMEM_BYTES);
    cudaFuncSetAttribute(tc<0, 1, 0, 0>, cudaFuncAttributeMaxDynamicSharedMemorySize, SMEM_BYTES);
    cudaFuncSetAttribute(tc<0, 0, 0, 0>, cudaFuncAttributeMaxDynamicSharedMemorySize, SMEM_BYTES);
    cudaFuncSetAttribute(tc<1, 0, 2, 0>, cudaFuncAttributeMaxDynamicSharedMemorySize, SMEM_BYTES);
    cudaFuncSetAttribute(tc<0, 1, 1, 0>, cudaFuncAttributeMaxDynamicSharedMemorySize, SMEM_BYTES);

    const long CCs = (long)CC * CC;  // 65536

    // 0) zero atomically-accumulated row sums
    zeroS_kernel<<<4, 512>>>();

    // 1) Gram split-K: Mpart[s][b] = x1[b,:,chunk] * x0[b,:,chunk]^T, fused row sums
    tc<0, 0, 0, 1><<<2 * 2 * NSPLIT * BB, 256, SMEM_BYTES>>>(
        x1, CN, 128L * NN, 1024, NN,
        x0, CN, 128L * NN, 1024, NN,
        (float*)pMpart, CCs, (long)BB * CCs, 32768, 128, 256,
        nullptr, 0, (float*)pS1, (float*)pS0,
        1024, NSPLIT, 2, 2);

    // 2) reduce partials, bias-correction vectors
    reduceM_kernel<<<BB * CC * CC / 256, 256>>>();
    tvpv_kernel<<<256, 256>>>(theta_w, phi_w);

    // 3) T1[b] = theta_w * M[b]        (B from M[k][n] -> BTRANS)
    tc<0, 1, 0, 0><<<2 * 2 * BB, 256, SMEM_BYTES>>>(
        theta_w, 0, 128L * 256, 0, 256,
        (const float*)pM, CCs, 128, 0, 256,
        (float*)pT1, CCs, 0, 32768, 128, 256,
        nullptr, 0, nullptr, nullptr,
        256, 1, 2, 2);

    // 4) fraw[b] = T1[b] * phi_w^T     (phi_w natural [n][k])
    tc<0, 0, 0, 0><<<2 * 2 * BB, 256, SMEM_BYTES>>>(
        (const float*)pT1, CCs, 128L * 256, 0, 256,
        phi_w, 0, 128L * 256, 0, 256,
        (float*)pFraw, CCs, 0, 32768, 128, 256,
        nullptr, 0, nullptr, nullptr,
        256, 1, 2, 2);

    // 5) softmax over c (with bias corrections), tiled
    softmax_kernel<<<BB * 8, 256>>>(theta_b, phi_b);

    // 6) A2[b] = fS[b] * g_w           (B from g_w[k][n] -> BTRANS)
    tc<0, 1, 0, 0><<<2 * 2 * BB, 256, SMEM_BYTES>>>(
        (const float*)pFS, CCs, 128L * 256, 0, 256,
        g_w, 0, 128, 0, 256,
        (float*)pA2, CCs, 0, 32768, 128, 256,
        nullptr, 0, nullptr, nullptr,
        256, 1, 2, 2);

    // 7) cvec[b] = fS[b] * g_b
    cvec_kernel<<<256, 256>>>(g_b);

    // 8) yT[b][n][c] = sum_d x0[b][d][n] * A2[b][c][d] + cvec[b][c]
    tc<1, 0, 2, 0><<<128 * 2 * BB, 256, SMEM_BYTES>>>(
        x0, CN, 128, 0, NN,
        (const float*)pA2, CCs, 128L * 256, 0, 256,
        (float*)pYT, (long)NN * CC, 0, 128L * 256, 128, 256,
        (const float*)pCvec, CC, nullptr, nullptr,
        256, 1, 128, 2);

    // 9) out[b][o][q*256+c] = sum_ch W_w[o][ch] * yT[b][ch*64+q][c] + W_b[o]
    tc<0, 1, 1, 0><<<2 * 2 * 64 * BB, 256, SMEM_BYTES>>>(
        W_w, 0, 128L * 256, 0, 256,
        (const float*)pYT, CN, 128, 256, 16384,
        out, CN, 256, 128L * 16384, 128, 16384,
        W_b, 0, nullptr, nullptr,
        256, 64, 2, 2);
}

// round 16
// speedup vs baseline: 1.5009x; 1.5009x over previous
#include <cuda_runtime.h>
#include <cuda_bf16.h>
#include <cstdint>

#define BB 8
#define CC 256
#define NN 16384
#define NSPLIT 16
static const long CN = (long)CC * NN;

// ---------------- device scratch ----------------
__device__ float d_s0[BB * CC];
__device__ float d_s1[BB * CC];
__device__ float d_Mpart[(size_t)NSPLIT * BB * CC * CC];
__device__ float d_M[BB * CC * CC];
__device__ float d_T1[BB * CC * CC];
__device__ float d_fraw[BB * CC * CC];
__device__ float d_fS[BB * CC * CC];
__device__ float d_A2[BB * CC * CC];
__device__ float d_tvec[BB * CC];
__device__ float d_pvec[BB * CC];
__device__ float d_cvec[BB * CC];
__device__ float d_yT[(size_t)BB * NN * CC];

// ---------------- helpers ----------------
// packed split: hi = bf16x2(a,b), lo = bf16x2 of residuals. ~6 instructions.
__device__ __forceinline__ void split_pack2(float a, float b, uint32_t& hi, uint32_t& lo) {
    asm("cvt.rn.bf16x2.f32 %0, %1, %2;" : "=r"(hi) : "f"(b), "f"(a));
    float ha = __uint_as_float(hi << 16);           // f32 of bf16(a)
    float hb = __uint_as_float(hi & 0xffff0000u);   // f32 of bf16(b)
    asm("cvt.rn.bf16x2.f32 %0, %1, %2;" : "=r"(lo) : "f"(b - hb), "f"(a - ha));
}

__device__ __forceinline__ void mma_bf16(float* c, const uint32_t* a, const uint32_t* b) {
    asm volatile(
        "mma.sync.aligned.m16n8k16.row.col.f32.bf16.bf16.f32 "
        "{%0,%1,%2,%3},{%4,%5,%6,%7},{%8,%9},{%0,%1,%2,%3};"
        : "+f"(c[0]), "+f"(c[1]), "+f"(c[2]), "+f"(c[3])
        : "r"(a[0]), "r"(a[1]), "r"(a[2]), "r"(a[3]), "r"(b[0]), "r"(b[1]));
}

#define BK 32
#define KP 16          // k-pairs per chunk
#define ST 20          // smem row stride in b32 (pad 4) -> conflict-free frags

// ---------------- tensor-core GEMM: C[128m,128n] = A[128,K] * B[128n,K]^T ----------------
// A element [m][k]: ATRANS=0 -> Ap + m*aRS + k ; ATRANS=1 -> Ap + k*aRS + m
// B element [n][k]: BTRANS=0 -> Bp + n*bRS + k ; BTRANS=1 -> Bp + k*bRS + n
// BIAS: 0 none, 1 per-m-row, 2 per-n-col.  SUMS: atomicAdd fp32 row sums (gram only).
template <int ATRANS, int BTRANS, int BIAS, int SUMS>
__global__ __launch_bounds__(256, 2) void tc(
    const float* __restrict__ A, long aB, long aMT, long aS, long aRS,
    const float* __restrict__ B, long bB, long bNT, long bS, long bRS,
    float* __restrict__ C, long cB, long cS, long cMT, long cNT, long cLD,
    const float* __restrict__ bias, long biasB,
    float* __restrict__ sumA, float* __restrict__ sumB,
    int K, int nS, int nMT, int nNT) {
    __shared__ alignas(16) uint32_t sAhi[128 * ST], sAlo[128 * ST];
    __shared__ alignas(16) uint32_t sBhi[128 * ST], sBlo[128 * ST];

    const int tid = threadIdx.x;
    const int lane = tid & 31;
    const int wid = tid >> 5;
    const int wm = wid >> 1;   // 0..3
    const int wn = wid & 1;    // 0..1
    const int g = lane >> 2;   // group row 0..7
    const int t4 = lane & 3;   // 0..3

    int z = blockIdx.x;
    const int nt = z % nNT; z /= nNT;
    const int mt = z % nMT; z /= nMT;
    const int s = z % nS;
    const int b = z / nS;

    const float* Ap = A + (size_t)b * aB + (size_t)mt * aMT + (size_t)s * aS;
    const float* Bp = B + (size_t)b * bB + (size_t)nt * bNT + (size_t)s * bS;
    float* Cp = C + (size_t)b * cB + (size_t)s * cS + (size_t)mt * cMT + (size_t)nt * cNT;

    float acc[2][8][4];
#pragma unroll
    for (int i = 0; i < 2; i++)
#pragma unroll
        for (int j = 0; j < 8; j++)
#pragma unroll
            for (int q = 0; q < 4; q++) acc[i][j][q] = 0.f;

    const int nch = K / BK;
    for (int ch = 0; ch < nch; ch++) {
        const int kt = ch * BK;
        // ---- stage A ----
        if (!ATRANS) {
            // float4 loads: 8 float4 per 32-k row
#pragma unroll
            for (int i = tid; i < 128 * 8; i += 256) {
                int r = i >> 3, q = i & 7;
                float4 v = *(const float4*)(Ap + (size_t)r * aRS + kt + 4 * q);
                uint32_t h0, l0, h1, l1;
                split_pack2(v.x, v.y, h0, l0);
                split_pack2(v.z, v.w, h1, l1);
                *(uint2*)&sAhi[r * ST + 2 * q] = make_uint2(h0, h1);
                *(uint2*)&sAlo[r * ST + 2 * q] = make_uint2(l0, l1);
                if (SUMS && nt == 0) {
                    float red = (v.x + v.y) + (v.z + v.w);
#pragma unroll
                    for (int qq = 4; qq; qq >>= 1) red += __shfl_xor_sync(0xffffffffu, red, qq);
                    if ((lane & 7) == 0) atomicAdd(&sumA[(size_t)b * CC + mt * 128 + r], red);
                }
            }
        } else {
#pragma unroll
            for (int i = tid; i < 128 * KP; i += 256) {
                int m = i & 127, cp = i >> 7;
                float v0 = Ap[(size_t)(kt + 2 * cp) * aRS + m];
                float v1 = Ap[(size_t)(kt + 2 * cp + 1) * aRS + m];
                uint32_t hi, lo;
                split_pack2(v0, v1, hi, lo);
                sAhi[m * ST + cp] = hi;
                sAlo[m * ST + cp] = lo;
            }
        }
        // ---- stage B ----
        if (!BTRANS) {
#pragma unroll
            for (int i = tid; i < 128 * 8; i += 256) {
                int r = i >> 3, q = i & 7;
                float4 v = *(const float4*)(Bp + (size_t)r * bRS + kt + 4 * q);
                uint32_t h0, l0, h1, l1;
                split_pack2(v.x, v.y, h0, l0);
                split_pack2(v.z, v.w, h1, l1);
                *(uint2*)&sBhi[r * ST + 2 * q] = make_uint2(h0, h1);
                *(uint2*)&sBlo[r * ST + 2 * q] = make_uint2(l0, l1);
                if (SUMS && mt == 0) {
                    float red = (v.x + v.y) + (v.z + v.w);
#pragma unroll
                    for (int qq = 4; qq; qq >>= 1) red += __shfl_xor_sync(0xffffffffu, red, qq);
                    if ((lane & 7) == 0) atomicAdd(&sumB[(size_t)b * CC + nt * 128 + r], red);
                }
            }
        } else {
#pragma unroll
            for (int i = tid; i < 128 * KP; i += 256) {
                int n = i & 127, cp = i >> 7;
                float v0 = Bp[(size_t)(kt + 2 * cp) * bRS + n];
                float v1 = Bp[(size_t)(kt + 2 * cp + 1) * bRS + n];
                uint32_t hi, lo;
                split_pack2(v0, v1, hi, lo);
                sBhi[n * ST + cp] = hi;
                sBlo[n * ST + cp] = lo;
            }
        }
        __syncthreads();

        // ---- compute: two k16 steps ----
#pragma unroll
        for (int kk = 0; kk < 2; kk++) {
            const int kb = kk * 8;
            uint32_t af[2][2][4];
#pragma unroll
            for (int mi = 0; mi < 2; mi++) {
                int r = wm * 32 + mi * 16 + g;
#pragma unroll
                for (int p = 0; p < 2; p++) {
                    const uint32_t* S = p ? sAlo : sAhi;
                    af[mi][p][0] = S[r * ST + kb + t4];
                    af[mi][p][1] = S[(r + 8) * ST + kb + t4];
                    af[mi][p][2] = S[r * ST + kb + t4 + 4];
                    af[mi][p][3] = S[(r + 8) * ST + kb + t4 + 4];
                }
            }
            uint32_t bf[8][2][2];
#pragma unroll
            for (int ni = 0; ni < 8; ni++) {
                int n = wn * 64 + ni * 8 + g;
#pragma unroll
                for (int p = 0; p < 2; p++) {
                    const uint32_t* S = p ? sBlo : sBhi;
                    bf[ni][p][0] = S[n * ST + kb + t4];
                    bf[ni][p][1] = S[n * ST + kb + t4 + 4];
                }
            }
#pragma unroll
            for (int mi = 0; mi < 2; mi++)
#pragma unroll
                for (int ni = 0; ni < 8; ni++) {
                    mma_bf16(acc[mi][ni], af[mi][0], bf[ni][0]);  // hi*hi
                    mma_bf16(acc[mi][ni], af[mi][0], bf[ni][1]);  // hi*lo
                    mma_bf16(acc[mi][ni], af[mi][1], bf[ni][0]);  // lo*hi
                }
        }
        __syncthreads();
    }

    // ---- epilogue ----
#pragma unroll
    for (int mi = 0; mi < 2; mi++) {
        int r0 = wm * 32 + mi * 16 + g;
        float bm0 = 0.f, bm1 = 0.f;
        if (BIAS == 1) {
            bm0 = bias[(size_t)b * biasB + mt * 128 + r0];
            bm1 = bias[(size_t)b * biasB + mt * 128 + r0 + 8];
        }
#pragma unroll
        for (int ni = 0; ni < 8; ni++) {
            int cn = wn * 64 + ni * 8 + t4 * 2;
            float bc0 = 0.f, bc1 = 0.f;
            if (BIAS == 2) {
                bc0 = bias[(size_t)b * biasB + nt * 128 + cn];
                bc1 = bias[(size_t)b * biasB + nt * 128 + cn + 1];
            }
            float2 v0 = {acc[mi][ni][0] + bm0 + bc0, acc[mi][ni][1] + bm0 + bc1};
            float2 v1 = {acc[mi][ni][2] + bm1 + bc0, acc[mi][ni][3] + bm1 + bc1};
            *(float2*)(Cp + (size_t)r0 * cLD + cn) = v0;
            *(float2*)(Cp + (size_t)(r0 + 8) * cLD + cn) = v1;
        }
    }
}

// ---------------- small kernels ----------------
__global__ void zeroS_kernel() {
    int i = blockIdx.x * 512 + threadIdx.x;
    if (i < BB * CC) { d_s0[i] = 0.f; d_s1[i] = 0.f; }
}
__global__ void reduceM_kernel() {
    int idx = blockIdx.x * 256 + threadIdx.x;
    float acc = 0.f;
#pragma unroll
    for (int s = 0; s < NSPLIT; s++) acc += d_Mpart[(size_t)s * BB * CC * CC + idx];
    d_M[idx] = acc;
}
// one warp per (b,c): tv = theta_w[c,:]·s1[b], pv = phi_w[c,:]·s0[b]
__global__ void tvpv_kernel(const float* __restrict__ theta_w,
                            const float* __restrict__ phi_w) {
    int w = blockIdx.x * 8 + (threadIdx.x >> 5);
    int lane = threadIdx.x & 31;
    int b = w >> 8, c = w & 255;
    float tv = 0.f, pv = 0.f;
#pragma unroll
    for (int i = lane; i < CC; i += 32) {
        float s1v = d_s1[b * CC + i], s0v = d_s0[b * CC + i];
        tv += theta_w[c * CC + i] * s1v;
        pv += phi_w[c * CC + i] * s0v;
    }
#pragma unroll
    for (int q = 16; q; q >>= 1) {
        tv += __shfl_xor_sync(0xffffffffu, tv, q);
        pv += __shfl_xor_sync(0xffffffffu, pv, q);
    }
    if (lane == 0) {
        d_tvec[b * CC + c] = tv;
        d_pvec[b * CC + c] = pv;
    }
}
// tiled softmax over axis c: block = (b, 32-wide d tile); coalesced gmem access
__global__ __launch_bounds__(256) void softmax_kernel(const float* __restrict__ theta_b,
                                                      const float* __restrict__ phi_b) {
    const int b = blockIdx.x >> 3;
    const int d0 = (blockIdx.x & 7) * 32;
    __shared__ float tile[256][33];
    __shared__ float stv[256], stb[256], spb[32], spv[32];
    __shared__ float red[8][33];
    __shared__ float colmax[32], colsum[32];
    const int tid = threadIdx.x;
    const int j = tid & 31, p = tid >> 5;

    if (tid < 256) {
        stv[tid] = d_tvec[b * CC + tid];
        stb[tid] = theta_b[tid];
    }
    if (tid < 32) {
        spb[tid] = phi_b[d0 + tid];
        spv[tid] = d_pvec[b * CC + d0 + tid];
    }
    __syncthreads();

    for (int idx = tid; idx < 256 * 32; idx += 256) {
        int c = idx >> 5, jj = idx & 31;
        float l = d_fraw[((size_t)b * CC + c) * CC + d0 + jj] + spb[jj] * stv[c] +
                  stb[c] * (spv[jj] + (float)NN * spb[jj]);
        tile[c][jj] = l;
    }
    __syncthreads();

    float m = -3.4e38f;
#pragma unroll
    for (int r = 0; r < 32; r++) m = fmaxf(m, tile[p * 32 + r][j]);
    red[p][j] = m;
    __syncthreads();
    if (p == 0) {
        float mm = red[0][j];
#pragma unroll
        for (int q = 1; q < 8; q++) mm = fmaxf(mm, red[q][j]);
        colmax[j] = mm;
    }
    __syncthreads();

    float cm = colmax[j];
    float s = 0.f;
#pragma unroll
    for (int r = 0; r < 32; r++) {
        float e = expf(tile[p * 32 + r][j] - cm);
        tile[p * 32 + r][j] = e;
        s += e;
    }
    red[p][j] = s;
    __syncthreads();
    if (p == 0) {
        float ss = red[0][j];
#pragma unroll
        for (int q = 1; q < 8; q++) ss += red[q][j];
        colsum[j] = 1.f / ss;
    }
    __syncthreads();

    for (int idx = tid; idx < 256 * 32; idx += 256) {
        int c = idx >> 5, jj = idx & 31;
        d_fS[((size_t)b * CC + c) * CC + d0 + jj] = tile[c][jj] * colsum[jj];
    }
}
// one warp per (b,c): cvec = fS[b][c][:]·g_b
__global__ void cvec_kernel(const float* __restrict__ g_b) {
    int w = blockIdx.x * 8 + (threadIdx.x >> 5);
    int lane = threadIdx.x & 31;
    int b = w >> 8, c = w & 255;
    const float* row = d_fS + ((size_t)b * CC + c) * CC;
    float acc = 0.f;
#pragma unroll
    for (int i = lane; i < CC; i += 32) acc += row[i] * g_b[i];
#pragma unroll
    for (int q = 16; q; q >>= 1) acc += __shfl_xor_sync(0xffffffffu, acc, q);
    if (lane == 0) d_cvec[b * CC + c] = acc;
}

// ---------------- launch ----------------
extern "C" void kernel_launch(void* const* d_in, const int* in_sizes, int n_in,
                              void* d_out, int out_size) {
    const float* x0 = (const float*)d_in[0];
    const float* x1 = (const float*)d_in[1];
    const float* g_w = (const float*)d_in[2];
    const float* g_b = (const float*)d_in[3];
    const float* theta_w = (const float*)d_in[4];
    const float* theta_b = (const float*)d_in[5];
    const float* phi_w = (const float*)d_in[6];
    const float* phi_b = (const float*)d_in[7];
    const float* W_w = (const float*)d_in[8];
    const float* W_b = (const float*)d_in[9];
    float* out = (float*)d_out;

    void *pMpart, *pM, *pT1, *pFraw, *pFS, *pA2, *pYT, *pCvec, *pS0, *pS1;
    cudaGetSymbolAddress(&pMpart, d_Mpart);
    cudaGetSymbolAddress(&pM, d_M);
    cudaGetSymbolAddress(&pT1, d_T1);
    cudaGetSymbolAddress(&pFraw, d_fraw);
    cudaGetSymbolAddress(&pFS, d_fS);
    cudaGetSymbolAddress(&pA2, d_A2);
    cudaGetSymbolAddress(&pYT, d_yT);
    cudaGetSymbolAddress(&pCvec, d_cvec);
    cudaGetSymbolAddress(&pS0, d_s0);
    cudaGetSymbolAddress(&pS1, d_s1);

    const long CCs = (long)CC * CC;  // 65536

    // 0) zero atomically-accumulated row sums
    zeroS_kernel<<<4, 512>>>();

    // 1) Gram split-K: Mpart[s][b] = x1[b,:,chunk] * x0[b,:,chunk]^T, fused row sums
    tc<0, 0, 0, 1><<<2 * 2 * NSPLIT * BB, 256>>>(
        x1, CN, 128L * NN, 1024, NN,
        x0, CN, 128L * NN, 1024, NN,
        (float*)pMpart, CCs, (long)BB * CCs, 32768, 128, 256,
        nullptr, 0, (float*)pS1, (float*)pS0,
        1024, NSPLIT, 2, 2);

    // 2) reduce partials, bias-correction vectors
    reduceM_kernel<<<BB * CC * CC / 256, 256>>>();
    tvpv_kernel<<<256, 256>>>(theta_w, phi_w);

    // 3) T1[b] = theta_w * M[b]        (B from M[k][n] -> BTRANS)
    tc<0, 1, 0, 0><<<2 * 2 * BB, 256>>>(
        theta_w, 0, 128L * 256, 0, 256,
        (const float*)pM, CCs, 128, 0, 256,
        (float*)pT1, CCs, 0, 32768, 128, 256,
        nullptr, 0, nullptr, nullptr,
        256, 1, 2, 2);

    // 4) fraw[b] = T1[b] * phi_w^T     (phi_w natural [n][k])
    tc<0, 0, 0, 0><<<2 * 2 * BB, 256>>>(
        (const float*)pT1, CCs, 128L * 256, 0, 256,
        phi_w, 0, 128L * 256, 0, 256,
        (float*)pFraw, CCs, 0, 32768, 128, 256,
        nullptr, 0, nullptr, nullptr,
        256, 1, 2, 2);

    // 5) softmax over c (with bias corrections), tiled
    softmax_kernel<<<BB * 8, 256>>>(theta_b, phi_b);

    // 6) A2[b] = fS[b] * g_w           (B from g_w[k][n] -> BTRANS)
    tc<0, 1, 0, 0><<<2 * 2 * BB, 256>>>(
        (const float*)pFS, CCs, 128L * 256, 0, 256,
        g_w, 0, 128, 0, 256,
        (float*)pA2, CCs, 0, 32768, 128, 256,
        nullptr, 0, nullptr, nullptr,
        256, 1, 2, 2);

    // 7) cvec[b] = fS[b] * g_b
    cvec_kernel<<<256, 256>>>(g_b);

    // 8) yT[b][n][c] = sum_d x0[b][d][n] * A2[b][c][d] + cvec[b][c]
    tc<1, 0, 2, 0><<<128 * 2 * BB, 256>>>(
        x0, CN, 128, 0, NN,
        (const float*)pA2, CCs, 128L * 256, 0, 256,
        (float*)pYT, (long)NN * CC, 0, 128L * 256, 128, 256,
        (const float*)pCvec, CC, nullptr, nullptr,
        256, 1, 128, 2);

    // 9) out[b][o][q*256+c] = sum_ch W_w[o][ch] * yT[b][ch*64+q][c] + W_b[o]
    tc<0, 1, 1, 0><<<2 * 2 * 64 * BB, 256>>>(
        W_w, 0, 128L * 256, 0, 256,
        (const float*)pYT, CN, 128, 256, 16384,
        out, CN, 256, 128L * 16384, 128, 16384,
        W_b, 0, nullptr, nullptr,
        256, 64, 2, 2);
}